// round 13
// baseline (speedup 1.0000x reference)
#include <cuda_runtime.h>
#include <cuda_bf16.h>
#include <cstdint>

// Problem shape (fixed by the dataset)
#define B_ 8
#define T_ 4096
#define F_ 512
#define ROWS_ (B_ * T_)

#define GRID_ 148          // 1 CTA per SM; all co-resident
#define BLK_  1024

#define TROWS 64                       // rows per work ticket
#define NTICK (ROWS_ / TROWS)          // 512 tickets per phase

// Scratch (no allocations allowed) — device globals.
__device__ float g_z[ROWS_];        // linear scores (monotone-equiv. for peaks)
__device__ int   g_idx[ROWS_];      // per batch: compact list of peak t's
__device__ int   g_hlens[B_];       // peak counts per batch
__device__ unsigned g_tick1 = 0;    // phase-1 ticket counter
__device__ unsigned g_tick2 = 0;    // phase-3 ticket counter
__device__ unsigned g_bar_count = 0;
__device__ unsigned g_bar_gen   = 0;

// Software grid barrier (all 148 CTAs co-resident at 1 CTA/SM).
// The releasing master also resets *rst (ticket counter) before release.
__device__ __forceinline__ void grid_barrier(unsigned* rst) {
    __syncthreads();
    if (threadIdx.x == 0) {
        unsigned gen = *(volatile unsigned*)&g_bar_gen;
        __threadfence();                       // publish this block's phase writes
        unsigned arr = atomicAdd(&g_bar_count, 1u);
        if (arr == GRID_ - 1) {
            atomicExch(&g_bar_count, 0u);
            if (rst) *rst = 0u;
            __threadfence();
            atomicAdd(&g_bar_gen, 1u);         // release
        } else {
            while (*(volatile unsigned*)&g_bar_gen == gen) { }
        }
        __threadfence();                       // acquire other blocks' writes
    }
    __syncthreads();
}

__global__ void __launch_bounds__(BLK_, 1)
k_fused(const float* __restrict__ feat, const float* __restrict__ W,
        float* __restrict__ out, int out_size) {
    const int tid  = threadIdx.x;
    const int lane = tid & 31;
    const int wid  = tid >> 5;                 // 0..31
    const int bid  = blockIdx.x;

    __shared__ int warp_sums[32];
    __shared__ int warp_incl[32];
    __shared__ int s_hl[B_];
    __shared__ unsigned s_tk;

    // ------------------------------------------------------------------
    // Phase 1: GEMV with work stealing. Ticket = 64 rows; warp wid does
    // rows tk*64 + wid*2 and +1 (8 independent LDG.128 per warp).
    {
        const float4* w4 = reinterpret_cast<const float4*>(W);
        float4 wreg[4];
#pragma unroll
        for (int i = 0; i < 4; i++) wreg[i] = w4[lane + i * 32];

        for (;;) {
            if (tid == 0) s_tk = atomicAdd(&g_tick1, 1u);
            __syncthreads();
            const unsigned tk = s_tk;
            __syncthreads();                   // s_tk consumed before next write
            if (tk >= NTICK) break;

            const int r0 = (int)tk * TROWS + wid * 2;
            const float4* f0 = reinterpret_cast<const float4*>(feat + (size_t)(r0 + 0) * F_);
            const float4* f1 = reinterpret_cast<const float4*>(feat + (size_t)(r0 + 1) * F_);
            float s0 = 0.f, s1 = 0.f;
#pragma unroll
            for (int i = 0; i < 4; i++) {
                const int idx = lane + i * 32;
                const float4 w = wreg[i];
                float4 a0 = f0[idx];
                float4 a1 = f1[idx];
                s0 += a0.x * w.x + a0.y * w.y + a0.z * w.z + a0.w * w.w;
                s1 += a1.x * w.x + a1.y * w.y + a1.z * w.z + a1.w * w.w;
            }
#pragma unroll
            for (int o = 16; o > 0; o >>= 1) {
                s0 += __shfl_down_sync(0xFFFFFFFFu, s0, o);
                s1 += __shfl_down_sync(0xFFFFFFFFu, s1, o);
            }
            if (lane == 0) {
                g_z[r0 + 0] = s0;
                g_z[r0 + 1] = s1;
            }
        }
    }

    grid_barrier(&g_tick2);                    // reset phase-3 tickets

    // ------------------------------------------------------------------
    // Phase 2: blocks 0..7 — peak detect + compact gather list per batch.
    if (bid < B_) {
        const int b = bid;
        const float* zb = g_z + b * T_;
        const int t0 = tid * 4;                // 1024 threads * 4 = 4096

        int flags[4];
        int cnt = 0;
#pragma unroll
        for (int k = 0; k < 4; k++) {
            int t = t0 + k;
            float c = zb[t];
            float l = (t > 0)      ? zb[t - 1] : c;
            float r = (t < T_ - 1) ? zb[t + 1] : c;
            flags[k] = (c >= l) & (c >= r);
            cnt += flags[k];
        }

        int v = cnt;
#pragma unroll
        for (int o = 1; o < 32; o <<= 1) {
            int n = __shfl_up_sync(0xFFFFFFFFu, v, o);
            if (lane >= o) v += n;
        }
        if (lane == 31) warp_sums[wid] = v;
        __syncthreads();
        if (wid == 0) {
            int s = warp_sums[lane];
#pragma unroll
            for (int o = 1; o < 32; o <<= 1) {
                int n = __shfl_up_sync(0xFFFFFFFFu, s, o);
                if (lane >= o) s += n;
            }
            warp_incl[lane] = s;
        }
        __syncthreads();

        int excl = (v - cnt) + (wid > 0 ? warp_incl[wid - 1] : 0);
#pragma unroll
        for (int k = 0; k < 4; k++) {
            int t = t0 + k;
            if (flags[k]) g_idx[b * T_ + excl] = t;
            excl += flags[k];
        }
        if (tid == 0) {
            int hl = warp_incl[31];
            g_hlens[b] = hl;
            if (out_size >= ROWS_ * F_ + B_)
                out[(size_t)ROWS_ * F_ + b] = (float)hl;
        }
    }

    grid_barrier(&g_tick1);                    // reset phase-1 tickets (next replay)

    // ------------------------------------------------------------------
    // Phase 3: destination-centric writer with work stealing.
    // Ticket = 64 dest rows; 8 groups of 128 threads x 8 rows each.
    // Row (b, i): i < hl[b] -> copy feat row g_idx[b][i], else zero.
    {
        if (tid < B_) s_hl[tid] = g_hlens[tid];
        __syncthreads();

        const int sub = tid >> 7;              // 0..7: group id
        const int j   = tid & 127;             // float4 index within row
        const float4 z4 = make_float4(0.f, 0.f, 0.f, 0.f);

        for (;;) {
            if (tid == 0) s_tk = atomicAdd(&g_tick2, 1u);
            __syncthreads();
            const unsigned tk = s_tk;
            __syncthreads();
            if (tk >= NTICK) break;

            const int base0 = (int)tk * TROWS + sub * 8;
#pragma unroll
            for (int half = 0; half < 2; half++) {
                const int base = base0 + half * 4;
                int src[4];
#pragma unroll
                for (int k = 0; k < 4; k++) {
                    const int row = base + k;
                    const int b = row >> 12;   // T_ = 4096
                    const int i = row & (T_ - 1);
                    src[k] = (i < s_hl[b]) ? (b * T_ + g_idx[row]) : -1;
                }
                float4 v4[4];
#pragma unroll
                for (int k = 0; k < 4; k++)
                    v4[k] = (src[k] >= 0)
                        ? reinterpret_cast<const float4*>(feat + (size_t)src[k] * F_)[j]
                        : z4;
#pragma unroll
                for (int k = 0; k < 4; k++)
                    __stcs(&reinterpret_cast<float4*>(out + (size_t)(base + k) * F_)[j], v4[k]);
            }
        }
    }
}

extern "C" void kernel_launch(void* const* d_in, const int* in_sizes, int n_in,
                              void* d_out, int out_size) {
    const float* feat = (const float*)d_in[0];
    const float* W    = (const float*)d_in[1];
    float* out        = (float*)d_out;
    k_fused<<<GRID_, BLK_>>>(feat, W, out, out_size);
}

// round 14
// speedup vs baseline: 1.0383x; 1.0383x over previous
#include <cuda_runtime.h>
#include <cuda_bf16.h>
#include <cstdint>

// Problem shape (fixed by the dataset)
#define B_ 8
#define T_ 4096
#define F_ 512
#define ROWS_ (B_ * T_)

#define GRID_ 148          // 1 CTA per SM; all co-resident
#define BLK_  1024

// Scratch (no allocations allowed) — device globals.
__device__ float g_z[ROWS_];        // linear scores (monotone-equiv. for peaks)
__device__ int   g_idx[ROWS_];      // per batch: compact list of peak t's
__device__ int   g_hlens[B_];       // peak counts per batch
__device__ unsigned g_bar_count = 0;
__device__ unsigned g_bar_gen   = 0;

// Software grid barrier (all 148 CTAs co-resident at 1 CTA/SM).
__device__ __forceinline__ void grid_barrier() {
    __syncthreads();
    if (threadIdx.x == 0) {
        unsigned gen = *(volatile unsigned*)&g_bar_gen;
        __threadfence();                       // publish this block's phase writes
        unsigned arr = atomicAdd(&g_bar_count, 1u);
        if (arr == GRID_ - 1) {
            atomicExch(&g_bar_count, 0u);
            __threadfence();
            atomicAdd(&g_bar_gen, 1u);         // release
        } else {
            while (*(volatile unsigned*)&g_bar_gen == gen) { }
        }
        __threadfence();                       // acquire other blocks' writes
    }
    __syncthreads();
}

__global__ void __launch_bounds__(BLK_, 1)
k_fused(const float* __restrict__ feat, const float* __restrict__ W,
        float* __restrict__ out, int out_size) {
    const int tid  = threadIdx.x;
    const int lane = tid & 31;
    const int wid  = tid >> 5;                 // 0..31
    const int bid  = blockIdx.x;

    __shared__ int warp_sums[32];
    __shared__ int warp_incl[32];
    __shared__ int s_hl[B_];

    // ------------------------------------------------------------------
    // Phase 1: GEMV (reads) + unconditional zero-fill of out, with PLAIN
    // write-back stores so the 126MB L2 absorbs the zeros (they get
    // overwritten in-cache by phase 3 for peak rows; only the final image
    // drains to DRAM lazily). 4 rows per warp per iteration.
    {
        const float4* w4 = reinterpret_cast<const float4*>(W);
        float4 wreg[4];
#pragma unroll
        for (int i = 0; i < 4; i++) wreg[i] = w4[lane + i * 32];
        const float4 z4 = make_float4(0.f, 0.f, 0.f, 0.f);

        for (int row0 = bid * 128 + wid * 4; row0 < ROWS_; row0 += GRID_ * 128) {
            const float4* f0 = reinterpret_cast<const float4*>(feat + (size_t)(row0 + 0) * F_);
            const float4* f1 = reinterpret_cast<const float4*>(feat + (size_t)(row0 + 1) * F_);
            const float4* f2 = reinterpret_cast<const float4*>(feat + (size_t)(row0 + 2) * F_);
            const float4* f3 = reinterpret_cast<const float4*>(feat + (size_t)(row0 + 3) * F_);

            // All 16 loads issued up front.
            float4 a[4][4];
#pragma unroll
            for (int i = 0; i < 4; i++) {
                const int idx = lane + i * 32;
                a[0][i] = f0[idx];
                a[1][i] = f1[idx];
                a[2][i] = f2[idx];
                a[3][i] = f3[idx];
            }

            // Zero-fill the same 4 output rows while loads are in flight.
#pragma unroll
            for (int r = 0; r < 4; r++) {
                float4* d = reinterpret_cast<float4*>(out + (size_t)(row0 + r) * F_);
#pragma unroll
                for (int i = 0; i < 4; i++)
                    d[lane + i * 32] = z4;
            }

            float s0 = 0.f, s1 = 0.f, s2 = 0.f, s3 = 0.f;
#pragma unroll
            for (int i = 0; i < 4; i++) {
                const float4 w = wreg[i];
                s0 += a[0][i].x * w.x + a[0][i].y * w.y + a[0][i].z * w.z + a[0][i].w * w.w;
                s1 += a[1][i].x * w.x + a[1][i].y * w.y + a[1][i].z * w.z + a[1][i].w * w.w;
                s2 += a[2][i].x * w.x + a[2][i].y * w.y + a[2][i].z * w.z + a[2][i].w * w.w;
                s3 += a[3][i].x * w.x + a[3][i].y * w.y + a[3][i].z * w.z + a[3][i].w * w.w;
            }
#pragma unroll
            for (int o = 16; o > 0; o >>= 1) {
                s0 += __shfl_down_sync(0xFFFFFFFFu, s0, o);
                s1 += __shfl_down_sync(0xFFFFFFFFu, s1, o);
                s2 += __shfl_down_sync(0xFFFFFFFFu, s2, o);
                s3 += __shfl_down_sync(0xFFFFFFFFu, s3, o);
            }
            if (lane == 0) {
                g_z[row0 + 0] = s0;
                g_z[row0 + 1] = s1;
                g_z[row0 + 2] = s2;
                g_z[row0 + 3] = s3;
            }
        }
    }

    grid_barrier();

    // ------------------------------------------------------------------
    // Phase 2: blocks 0..7 — peak detect + compact gather list per batch.
    if (bid < B_) {
        const int b = bid;
        const float* zb = g_z + b * T_;
        const int t0 = tid * 4;                // 1024 threads * 4 = 4096

        int flags[4];
        int cnt = 0;
#pragma unroll
        for (int k = 0; k < 4; k++) {
            int t = t0 + k;
            float c = zb[t];
            float l = (t > 0)      ? zb[t - 1] : c;
            float r = (t < T_ - 1) ? zb[t + 1] : c;
            flags[k] = (c >= l) & (c >= r);
            cnt += flags[k];
        }

        int v = cnt;
#pragma unroll
        for (int o = 1; o < 32; o <<= 1) {
            int n = __shfl_up_sync(0xFFFFFFFFu, v, o);
            if (lane >= o) v += n;
        }
        if (lane == 31) warp_sums[wid] = v;
        __syncthreads();
        if (wid == 0) {
            int s = warp_sums[lane];
#pragma unroll
            for (int o = 1; o < 32; o <<= 1) {
                int n = __shfl_up_sync(0xFFFFFFFFu, s, o);
                if (lane >= o) s += n;
            }
            warp_incl[lane] = s;
        }
        __syncthreads();

        int excl = (v - cnt) + (wid > 0 ? warp_incl[wid - 1] : 0);
#pragma unroll
        for (int k = 0; k < 4; k++) {
            int t = t0 + k;
            if (flags[k]) g_idx[b * T_ + excl] = t;   // compact: i-th peak is t
            excl += flags[k];
        }
        if (tid == 0) {
            int hl = warp_incl[31];
            g_hlens[b] = hl;
            if (out_size >= ROWS_ * F_ + B_)
                out[(size_t)ROWS_ * F_ + b] = (float)hl;
        }
    }

    grid_barrier();

    // ------------------------------------------------------------------
    // Phase 3: gather-only copy (tail already zeroed in phase 1).
    // Dest row (b, i) with i < hl[b] gets feat row g_idx[b][i] — reads are
    // L2-resident, writes are coalesced plain write-back stores that
    // overwrite the zero lines while they are still in L2.
    // 1024 threads = 8 groups of 128; each group does 4 dest rows/iter.
    {
        if (tid < B_) s_hl[tid] = g_hlens[tid];
        __syncthreads();

        const int sub = tid >> 7;              // 0..7: group id
        const int j   = tid & 127;             // float4 index within row

        for (int base = bid * 32 + sub * 4; base < ROWS_; base += GRID_ * 32) {
            int src[4];
#pragma unroll
            for (int k = 0; k < 4; k++) {
                const int row = base + k;
                const int b = row >> 12;       // T_ = 4096
                const int i = row & (T_ - 1);
                src[k] = (i < s_hl[b]) ? (b * T_ + g_idx[row]) : -1;
            }
            float4 v4[4];
#pragma unroll
            for (int k = 0; k < 4; k++) {
                if (src[k] >= 0)
                    v4[k] = reinterpret_cast<const float4*>(feat + (size_t)src[k] * F_)[j];
            }
#pragma unroll
            for (int k = 0; k < 4; k++) {
                if (src[k] >= 0)
                    reinterpret_cast<float4*>(out + (size_t)(base + k) * F_)[j] = v4[k];
            }
        }
    }
}

extern "C" void kernel_launch(void* const* d_in, const int* in_sizes, int n_in,
                              void* d_out, int out_size) {
    const float* feat = (const float*)d_in[0];
    const float* W    = (const float*)d_in[1];
    float* out        = (float*)d_out;
    k_fused<<<GRID_, BLK_>>>(feat, W, out, out_size);
}